// round 14
// baseline (speedup 1.0000x reference)
#include <cuda_runtime.h>
#include <cuda_bf16.h>
#include <cstdint>

// ============================================================================
// out = patches @ (w_patch @ [w_reg|w_obj]) + bias, anchor decode.
//   kD : dummy (ncu ordinal shim; keeps kB at profiled ordinal)
//   kAf: FUSED W2 fold — full 768-deep dot products per CTA (grid 24,
//        block 384, double-buffered smem chunks), writes bf16 px-permuted
//        HMMA fragments directly (no partial round-trip, no 2nd kernel).
//   kB : R9-proven HMMA GEMM (K-split x4, N-split x2, px-permuted A
//        fragments as 2xLDG.128 __ldcs, B 1-ahead __ldg), grid 2048 x 256.
// ============================================================================

__device__ __align__(16) unsigned int g_Bfrag[48 * 6 * 32 * 2];

// ---------------------------------------------------------------------------
__global__ void kD() { if (threadIdx.x == 0) g_Bfrag[48 * 6 * 32 * 2 - 1] += 0; }

// ---------------------------------------------------------------------------
// kAf: grid 24, block 384. CTA: rows r0..r0+31 of W2, full K=768 in 12
// chunks of 64, double-buffered. Thread (jq=tid>>5 warp-uniform, rl=tid&31).
// ---------------------------------------------------------------------------
__global__ void __launch_bounds__(384) kAf(const float* __restrict__ w_patch,
                                           const float* __restrict__ w_reg,
                                           const float* __restrict__ w_obj)
{
    __shared__ __align__(16) float sWc[2][64 * 48];
    __shared__ float sWp[2][32 * 65];

    const int tid = threadIdx.x;
    const int r0  = blockIdx.x * 32;

    #define LOADCH(buf, ch) do {                                              \
        const int d0_ = (ch) * 64;                                            \
        _Pragma("unroll")                                                     \
        for (int i = tid; i < 64 * 48; i += 384) {                            \
            int d_ = i / 48, j_ = i % 48;                                     \
            float v_ = 0.f;                                                   \
            if (j_ < 36)      v_ = w_reg[(size_t)(d0_ + d_) * 36 + j_];       \
            else if (j_ < 45) v_ = w_obj[(size_t)(d0_ + d_) * 9 + (j_ - 36)]; \
            sWc[buf][i] = v_;                                                 \
        }                                                                     \
        _Pragma("unroll")                                                     \
        for (int i = tid; i < 32 * 64; i += 384) {                            \
            int r_ = i >> 6, d_ = i & 63;                                     \
            sWp[buf][r_ * 65 + d_] =                                          \
                w_patch[(size_t)(r0 + r_) * 768 + d0_ + d_];                  \
        }                                                                     \
    } while (0)

    LOADCH(0, 0);
    __syncthreads();

    const int jq = tid >> 5;          // warp-uniform -> broadcast LDS
    const int rl = tid & 31;
    float4 acc = make_float4(0.f, 0.f, 0.f, 0.f);

    for (int ch = 0; ch < 12; ++ch) {
        const int buf = ch & 1;
        if (ch + 1 < 12) LOADCH(buf ^ 1, ch + 1);
        #pragma unroll 8
        for (int dd = 0; dd < 64; ++dd) {
            float4 w = *(const float4*)&sWc[buf][dd * 48 + jq * 4];
            float  a = sWp[buf][rl * 65 + dd];
            acc.x += a * w.x; acc.y += a * w.y;
            acc.z += a * w.z; acc.w += a * w.w;
        }
        __syncthreads();
    }

    // scatter bf16 frags, px-permuted k mapping (as before):
    //   pc = r0+rl: st=pc>>4, px=pc&15, q=px&3, t4p=px>>2,
    //   k = (q<2) ? 2*t4p+q : 8+2*t4p+(q-2)
    const int pc = r0 + rl;
    const int st = pc >> 4, px = pc & 15;
    const int q = px & 3, t4p = px >> 2;
    const int k = (q < 2) ? (2 * t4p + q) : (8 + 2 * t4p + (q - 2));
    float sv[4] = {acc.x, acc.y, acc.z, acc.w};
    unsigned short* dst = (unsigned short*)g_Bfrag;
    #pragma unroll
    for (int c = 0; c < 4; ++c) {
        int j = jq * 4 + c;
        int tf = j >> 3;
        int lane = ((j & 7) << 2) | ((k >> 1) & 3);
        __nv_bfloat16 v = __float2bfloat16_rn(sv[c]);
        dst[(((st * 6 + tf) * 32 + lane) * 2 + (k >> 3)) * 2 + (k & 1)] =
            *(unsigned short*)&v;
    }
}

// ---------------------------------------------------------------------------
// kB: R9-proven. grid 2048 = ((b*32 + fy)*2 + cg), block 256 = 8 warps.
// Warp w: ks = w>>1 (12 K-steps), ns = w&1 (3 B-tiles). 16 cells/CTA.
// A: px-permuted fragments = 2 x LDG.128 __ldcs, 2-stage prefetch.
// B: 1-ahead __ldg double buffer. Epilogue: 4-way ks reduce + bias + decode.
// ---------------------------------------------------------------------------
#define SPART_OFF 0
#define BIAS_OFF  12544
#define TK_OFF    12736
#define TQ_OFF    12800
#define TBW_OFF   12864
#define TBH_OFF   12912
#define SMEMB     12992

__device__ __forceinline__ uint32_t smem_u32_kb(const void* p) {
    uint32_t a;
    asm("{ .reg .u64 t; cvta.to.shared.u64 t, %1; cvt.u32.u64 %0, t; }"
        : "=r"(a) : "l"(p));
    return a;
}

__global__ void __launch_bounds__(256, 5) kB(
    const float* __restrict__ img,
    const float* __restrict__ b_reg,
    const float* __restrict__ b_obj,
    float* __restrict__ out)
{
    extern __shared__ __align__(16) char sm[];
    const int tid  = threadIdx.x;
    const int wid  = tid >> 5;
    const int lane = tid & 31;
    const int cg   = blockIdx.x & 1;
    const int fy   = (blockIdx.x >> 1) & 31;
    const int b    = blockIdx.x >> 6;

    if (tid < 48) ((float*)(sm + BIAS_OFF))[tid] =
        (tid < 36) ? b_reg[tid] : ((tid < 45) ? b_obj[tid - 36] : 0.f);
    if (tid < 63) {
        ((unsigned char*)(sm + TK_OFF))[tid] = (unsigned char)(tid / 7);
        ((unsigned char*)(sm + TQ_OFF))[tid] = (unsigned char)(tid % 7);
    }
    if (tid < 9) {
        ((float*)(sm + TBW_OFF))[tid] = (float)(2 << (tid % 3));
        ((float*)(sm + TBH_OFF))[tid] = (float)(2 << (tid / 3));
    }

    const int ks = wid >> 1;
    const int ns = wid & 1;
    const int g  = lane >> 2;
    const int t4 = lane & 3;
    const int s0 = ks * 12;

    const float* base = img + ((size_t)(b * 3) * 512 + (size_t)fy * 16) * 512
                      + (cg * 16 + g) * 16 + 4 * t4;

    #define SOFF(s) ((size_t)((((s) >> 4) << 9) + ((s) & 15)) << 9)

    float d[3][4];
    #pragma unroll
    for (int t = 0; t < 3; ++t)
        #pragma unroll
        for (int q = 0; q < 4; ++q) d[t][q] = 0.f;

    const uint2* __restrict__ Bf = (const uint2*)g_Bfrag;

    #define LOADA(d0_, d1_, s) do {                  \
        const float* p_ = base + SOFF(s);            \
        d0_ = __ldcs((const float4*)(p_));           \
        d1_ = __ldcs((const float4*)(p_ + 128));     \
    } while (0)

    #define LOADB(B_, s) do {                                    \
        _Pragma("unroll")                                        \
        for (int t_ = 0; t_ < 3; ++t_)                           \
            B_[t_] = __ldg(&Bf[((s) * 6 + ns * 3 + t_) * 32 + lane]); \
    } while (0)

    #define COMPUTE(f0_, f1_, B_) do {                                        \
        uint32_t a0_, a1_, a2_, a3_;                                          \
        { __nv_bfloat162 h_ = __float22bfloat162_rn(make_float2(f0_.x, f0_.y)); a0_ = *(uint32_t*)&h_; } \
        { __nv_bfloat162 h_ = __float22bfloat162_rn(make_float2(f1_.x, f1_.y)); a1_ = *(uint32_t*)&h_; } \
        { __nv_bfloat162 h_ = __float22bfloat162_rn(make_float2(f0_.z, f0_.w)); a2_ = *(uint32_t*)&h_; } \
        { __nv_bfloat162 h_ = __float22bfloat162_rn(make_float2(f1_.z, f1_.w)); a3_ = *(uint32_t*)&h_; } \
        _Pragma("unroll")                                                     \
        for (int t_ = 0; t_ < 3; ++t_)                                        \
            asm volatile(                                                     \
                "mma.sync.aligned.m16n8k16.row.col.f32.bf16.bf16.f32 "        \
                "{%0,%1,%2,%3}, {%4,%5,%6,%7}, {%8,%9}, {%0,%1,%2,%3};"       \
                : "+f"(d[t_][0]), "+f"(d[t_][1]), "+f"(d[t_][2]), "+f"(d[t_][3]) \
                : "r"(a0_), "r"(a1_), "r"(a2_), "r"(a3_),                     \
                  "r"(B_[t_].x), "r"(B_[t_].y));                              \
    } while (0)

    float4 A0a, A0b, A1a, A1b;
    uint2  B0[3], B1[3];
    LOADA(A0a, A0b, s0);
    LOADA(A1a, A1b, s0 + 1);
    LOADB(B0, s0);

    #pragma unroll
    for (int i = 0; i < 6; ++i) {
        const int s  = s0 + 2 * i;
        const int n0 = (2 * i + 2 < 12) ? s + 2 : s0 + 11;
        const int n1 = (2 * i + 3 < 12) ? s + 3 : s0 + 11;
        LOADB(B1, s + 1);
        COMPUTE(A0a, A0b, B0);
        LOADA(A0a, A0b, n0);
        LOADB(B0, n0);
        COMPUTE(A1a, A1b, B1);
        LOADA(A1a, A1b, n1);
    }

    // ---- epilogue: partials to sPart[ks][16][49] (ns halves disjoint j) ----
    float* sPart = (float*)(sm + SPART_OFF);
    float* sBias = (float*)(sm + BIAS_OFF);
    #pragma unroll
    for (int cc = 0; cc < 2; ++cc) {
        const int cell = g + cc * 8;
        float* dst = sPart + (ks * 16 + cell) * 49;
        #pragma unroll
        for (int t = 0; t < 3; ++t) {
            const int j = (ns * 3 + t) * 8 + t4 * 2;
            dst[j]     = d[t][2 * cc];
            dst[j + 1] = d[t][2 * cc + 1];
        }
    }
    __syncthreads();

    // ---- reduce 4 ks partials (+bias) into sPart[0] ----
    #pragma unroll
    for (int i = 0; i < 4; ++i) {
        int idx = tid + 256 * i;
        if (idx < 16 * 49) {
            int j = idx % 49;
            if (j < 48) {
                sPart[idx] = sPart[idx] + sPart[idx + 16 * 49]
                           + sPart[idx + 2 * 16 * 49] + sPart[idx + 3 * 16 * 49]
                           + sBias[j];
            }
        }
    }
    __syncthreads();

    // ---- decode + coalesced store: 16 cells * 63 = 1008 floats ----
    const unsigned char* tK = (const unsigned char*)(sm + TK_OFF);
    const unsigned char* tQ = (const unsigned char*)(sm + TQ_OFF);
    const float* tBW = (const float*)(sm + TBW_OFF);
    const float* tBH = (const float*)(sm + TBH_OFF);
    float* obase = out + (size_t)blockIdx.x * 1008;
    const float bb_f = (float)b;
    const float fy_f = (float)fy * 16.f;
    const float fx0  = (float)(cg * 16);

    int cell = tid / 63;
    int r    = tid - cell * 63;
    int idx  = tid;
    #pragma unroll
    for (int i = 0; i < 4; ++i) {
        if (idx < 1008) {
            const int k = tK[r], q = tQ[r];
            const float* v = sPart + cell * 49;
            float res;
            if (q == 0)      res = (fx0 + (float)cell) * 16.f + v[4 * k];
            else if (q == 1) res = fy_f + v[4 * k + 1];
            else if (q == 2) res = (fx0 + (float)cell) * 16.f + v[4 * k] + tBW[k] * v[4 * k + 2];
            else if (q == 3) res = fy_f + v[4 * k + 1] + tBH[k] * v[4 * k + 3];
            else if (q == 4) res = bb_f;
            else if (q == 5) res = 1.f / (1.f + __expf(-v[36 + k]));
            else             res = (float)k;
            obase[idx] = res;
        }
        idx += 256; r += 4; cell += 4;
        if (r >= 63) { r -= 63; cell++; }
    }
}

// ---------------------------------------------------------------------------
extern "C" void kernel_launch(void* const* d_in, const int* in_sizes, int n_in,
                              void* d_out, int out_size)
{
    const float* img     = (const float*)d_in[0];
    const float* w_patch = (const float*)d_in[1];
    const float* w_reg   = (const float*)d_in[2];
    const float* b_reg   = (const float*)d_in[3];
    const float* w_obj   = (const float*)d_in[4];
    const float* b_obj   = (const float*)d_in[5];
    float* out = (float*)d_out;

    kD<<<1, 32>>>();                              // ordinal shim for ncu
    kAf<<<24, 384>>>(w_patch, w_reg, w_obj);

    cudaFuncSetAttribute(kB, cudaFuncAttributeMaxDynamicSharedMemorySize, SMEMB);
    kB<<<2048, 256, SMEMB>>>(img, b_reg, b_obj, out);
}

// round 15
// speedup vs baseline: 1.6396x; 1.6396x over previous
#include <cuda_runtime.h>
#include <cuda_bf16.h>
#include <cstdint>

// ============================================================================
// out = patches @ (w_patch @ [w_reg|w_obj]) + bias, anchor decode.
// TWO kernels only (per-graph-node cost ~3.4us measured, so count matters):
//   kA : W2 fold. 192 CTAs compute partials (R9-proven shape), grid-barrier
//        via self-resetting atomic counters, then each CTA reduces its
//        1/192 slice into bf16 px-permuted HMMA fragments.
//   kB : R9-proven HMMA GEMM (K-split x4, N-split x2, px-permuted A
//        fragments as 2xLDG.128 __ldcs, B 1-ahead __ldg), grid 2048 x 256.
// ============================================================================

__device__ float g_part[8 * 12 * 768 * 4];               // [p][jq][pc][4]
__device__ __align__(16) unsigned int g_Bfrag[48 * 6 * 32 * 2];
__device__ unsigned int g_c1;   // arrival counter (self-resets each run)
__device__ unsigned int g_c2;   // completion counter (self-resets each run)

// ---------------------------------------------------------------------------
// kA: grid (24, 8), block 384. Phase 1: partial W2 (rows r0..r0+31 x d-chunk
// of 96). Phase 2: grid barrier; each CTA reduces 48 float4 outputs.
// ---------------------------------------------------------------------------
__global__ void __launch_bounds__(384) kA(const float* __restrict__ w_patch,
                                          const float* __restrict__ w_reg,
                                          const float* __restrict__ w_obj)
{
    __shared__ __align__(16) float sWc[96 * 48];
    __shared__ float sWp[32 * 97];

    const int tid = threadIdx.x;
    const int r0  = blockIdx.x * 32;
    const int d0  = blockIdx.y * 96;

    // ---- phase 1: partial compute (R9 kA1 verbatim) ----
    #pragma unroll
    for (int i = tid; i < 96 * 48; i += 384) {
        int d = i / 48, j = i % 48;
        float v = 0.f;
        if (j < 36)       v = w_reg[(size_t)(d0 + d) * 36 + j];
        else if (j < 45)  v = w_obj[(size_t)(d0 + d) * 9 + (j - 36)];
        sWc[i] = v;
    }
    #pragma unroll
    for (int i = tid; i < 32 * 96; i += 384) {
        int r = i / 96, d = i % 96;
        sWp[r * 97 + d] = w_patch[(size_t)(r0 + r) * 768 + d0 + d];
    }
    __syncthreads();

    const int jq = tid >> 5;          // warp-uniform -> broadcast LDS
    const int rl = tid & 31;
    float4 acc = make_float4(0.f, 0.f, 0.f, 0.f);
    #pragma unroll 8
    for (int dd = 0; dd < 96; ++dd) {
        float4 w = *(const float4*)&sWc[dd * 48 + jq * 4];
        float  a = sWp[rl * 97 + dd];
        acc.x += a * w.x; acc.y += a * w.y; acc.z += a * w.z; acc.w += a * w.w;
    }
    ((float4*)g_part)[((size_t)blockIdx.y * 12 + jq) * 768 + r0 + rl] = acc;

    // ---- grid barrier (all 192 CTAs co-resident: 2 CTAs/SM x 148 >= 192) --
    __threadfence();
    __syncthreads();
    if (tid == 0) {
        atomicAdd(&g_c1, 1u);
        while (*(volatile unsigned int*)&g_c1 < 192u) { }
    }
    __syncthreads();
    __threadfence();

    // ---- phase 2: this CTA reduces outputs [slice*48, slice*48+48) ----
    const int slice = blockIdx.y * 24 + blockIdx.x;
    if (tid < 48) {
        const int o  = slice * 48 + tid;      // float4 output index
        const int pc = o % 768;
        const int jqo = o / 768;
        const float4* p4 = (const float4*)g_part;
        float4 s = make_float4(0.f, 0.f, 0.f, 0.f);
        #pragma unroll
        for (int p = 0; p < 8; ++p) {
            float4 v = p4[(size_t)p * 9216 + o];
            s.x += v.x; s.y += v.y; s.z += v.z; s.w += v.w;
        }
        float sv[4] = {s.x, s.y, s.z, s.w};
        // px-permuted frag mapping
        const int st = pc >> 4, px = pc & 15;
        const int q = px & 3, t4p = px >> 2;
        const int k = (q < 2) ? (2 * t4p + q) : (8 + 2 * t4p + (q - 2));
        unsigned short* dst = (unsigned short*)g_Bfrag;
        #pragma unroll
        for (int c = 0; c < 4; ++c) {
            int j = jqo * 4 + c;
            int tf = j >> 3;
            int lane = ((j & 7) << 2) | ((k >> 1) & 3);
            __nv_bfloat16 v = __float2bfloat16_rn(sv[c]);
            dst[(((st * 6 + tf) * 32 + lane) * 2 + (k >> 3)) * 2 + (k & 1)] =
                *(unsigned short*)&v;
        }
    }
    __syncthreads();

    // ---- completion count; last CTA resets counters for next invocation --
    if (tid == 0) {
        __threadfence();
        unsigned int r = atomicAdd(&g_c2, 1u);
        if (r == 191u) {                      // all CTAs past spin + reduce
            atomicExch(&g_c1, 0u);
            atomicExch(&g_c2, 0u);
        }
    }
}

// ---------------------------------------------------------------------------
// kB: R9-proven. grid 2048 = ((b*32 + fy)*2 + cg), block 256 = 8 warps.
// Warp w: ks = w>>1 (12 K-steps), ns = w&1 (3 B-tiles). 16 cells/CTA.
// ---------------------------------------------------------------------------
#define SPART_OFF 0
#define BIAS_OFF  12544
#define TK_OFF    12736
#define TQ_OFF    12800
#define TBW_OFF   12864
#define TBH_OFF   12912
#define SMEMB     12992

__global__ void __launch_bounds__(256, 5) kB(
    const float* __restrict__ img,
    const float* __restrict__ b_reg,
    const float* __restrict__ b_obj,
    float* __restrict__ out)
{
    extern __shared__ __align__(16) char sm[];
    const int tid  = threadIdx.x;
    const int wid  = tid >> 5;
    const int lane = tid & 31;
    const int cg   = blockIdx.x & 1;
    const int fy   = (blockIdx.x >> 1) & 31;
    const int b    = blockIdx.x >> 6;

    if (tid < 48) ((float*)(sm + BIAS_OFF))[tid] =
        (tid < 36) ? b_reg[tid] : ((tid < 45) ? b_obj[tid - 36] : 0.f);
    if (tid < 63) {
        ((unsigned char*)(sm + TK_OFF))[tid] = (unsigned char)(tid / 7);
        ((unsigned char*)(sm + TQ_OFF))[tid] = (unsigned char)(tid % 7);
    }
    if (tid < 9) {
        ((float*)(sm + TBW_OFF))[tid] = (float)(2 << (tid % 3));
        ((float*)(sm + TBH_OFF))[tid] = (float)(2 << (tid / 3));
    }

    const int ks = wid >> 1;
    const int ns = wid & 1;
    const int g  = lane >> 2;
    const int t4 = lane & 3;
    const int s0 = ks * 12;

    const float* base = img + ((size_t)(b * 3) * 512 + (size_t)fy * 16) * 512
                      + (cg * 16 + g) * 16 + 4 * t4;

    #define SOFF(s) ((size_t)((((s) >> 4) << 9) + ((s) & 15)) << 9)

    float d[3][4];
    #pragma unroll
    for (int t = 0; t < 3; ++t)
        #pragma unroll
        for (int q = 0; q < 4; ++q) d[t][q] = 0.f;

    const uint2* __restrict__ Bf = (const uint2*)g_Bfrag;

    #define LOADA(d0_, d1_, s) do {                  \
        const float* p_ = base + SOFF(s);            \
        d0_ = __ldcs((const float4*)(p_));           \
        d1_ = __ldcs((const float4*)(p_ + 128));     \
    } while (0)

    #define LOADB(B_, s) do {                                    \
        _Pragma("unroll")                                        \
        for (int t_ = 0; t_ < 3; ++t_)                           \
            B_[t_] = __ldg(&Bf[((s) * 6 + ns * 3 + t_) * 32 + lane]); \
    } while (0)

    #define COMPUTE(f0_, f1_, B_) do {                                        \
        uint32_t a0_, a1_, a2_, a3_;                                          \
        { __nv_bfloat162 h_ = __float22bfloat162_rn(make_float2(f0_.x, f0_.y)); a0_ = *(uint32_t*)&h_; } \
        { __nv_bfloat162 h_ = __float22bfloat162_rn(make_float2(f1_.x, f1_.y)); a1_ = *(uint32_t*)&h_; } \
        { __nv_bfloat162 h_ = __float22bfloat162_rn(make_float2(f0_.z, f0_.w)); a2_ = *(uint32_t*)&h_; } \
        { __nv_bfloat162 h_ = __float22bfloat162_rn(make_float2(f1_.z, f1_.w)); a3_ = *(uint32_t*)&h_; } \
        _Pragma("unroll")                                                     \
        for (int t_ = 0; t_ < 3; ++t_)                                        \
            asm volatile(                                                     \
                "mma.sync.aligned.m16n8k16.row.col.f32.bf16.bf16.f32 "        \
                "{%0,%1,%2,%3}, {%4,%5,%6,%7}, {%8,%9}, {%0,%1,%2,%3};"       \
                : "+f"(d[t_][0]), "+f"(d[t_][1]), "+f"(d[t_][2]), "+f"(d[t_][3]) \
                : "r"(a0_), "r"(a1_), "r"(a2_), "r"(a3_),                     \
                  "r"(B_[t_].x), "r"(B_[t_].y));                              \
    } while (0)

    float4 A0a, A0b, A1a, A1b;
    uint2  B0[3], B1[3];
    LOADA(A0a, A0b, s0);
    LOADA(A1a, A1b, s0 + 1);
    LOADB(B0, s0);

    #pragma unroll
    for (int i = 0; i < 6; ++i) {
        const int s  = s0 + 2 * i;
        const int n0 = (2 * i + 2 < 12) ? s + 2 : s0 + 11;
        const int n1 = (2 * i + 3 < 12) ? s + 3 : s0 + 11;
        LOADB(B1, s + 1);
        COMPUTE(A0a, A0b, B0);
        LOADA(A0a, A0b, n0);
        LOADB(B0, n0);
        COMPUTE(A1a, A1b, B1);
        LOADA(A1a, A1b, n1);
    }

    // ---- epilogue: partials to sPart[ks][16][49] (ns halves disjoint j) ----
    float* sPart = (float*)(sm + SPART_OFF);
    float* sBias = (float*)(sm + BIAS_OFF);
    #pragma unroll
    for (int cc = 0; cc < 2; ++cc) {
        const int cell = g + cc * 8;
        float* dst = sPart + (ks * 16 + cell) * 49;
        #pragma unroll
        for (int t = 0; t < 3; ++t) {
            const int j = (ns * 3 + t) * 8 + t4 * 2;
            dst[j]     = d[t][2 * cc];
            dst[j + 1] = d[t][2 * cc + 1];
        }
    }
    __syncthreads();

    // ---- reduce 4 ks partials (+bias) into sPart[0] ----
    #pragma unroll
    for (int i = 0; i < 4; ++i) {
        int idx = tid + 256 * i;
        if (idx < 16 * 49) {
            int j = idx % 49;
            if (j < 48) {
                sPart[idx] = sPart[idx] + sPart[idx + 16 * 49]
                           + sPart[idx + 2 * 16 * 49] + sPart[idx + 3 * 16 * 49]
                           + sBias[j];
            }
        }
    }
    __syncthreads();

    // ---- decode + coalesced store: 16 cells * 63 = 1008 floats ----
    const unsigned char* tK = (const unsigned char*)(sm + TK_OFF);
    const unsigned char* tQ = (const unsigned char*)(sm + TQ_OFF);
    const float* tBW = (const float*)(sm + TBW_OFF);
    const float* tBH = (const float*)(sm + TBH_OFF);
    float* obase = out + (size_t)blockIdx.x * 1008;
    const float bb_f = (float)b;
    const float fy_f = (float)fy * 16.f;
    const float fx0  = (float)(cg * 16);

    int cell = tid / 63;
    int r    = tid - cell * 63;
    int idx  = tid;
    #pragma unroll
    for (int i = 0; i < 4; ++i) {
        if (idx < 1008) {
            const int k = tK[r], q = tQ[r];
            const float* v = sPart + cell * 49;
            float res;
            if (q == 0)      res = (fx0 + (float)cell) * 16.f + v[4 * k];
            else if (q == 1) res = fy_f + v[4 * k + 1];
            else if (q == 2) res = (fx0 + (float)cell) * 16.f + v[4 * k] + tBW[k] * v[4 * k + 2];
            else if (q == 3) res = fy_f + v[4 * k + 1] + tBH[k] * v[4 * k + 3];
            else if (q == 4) res = bb_f;
            else if (q == 5) res = 1.f / (1.f + __expf(-v[36 + k]));
            else             res = (float)k;
            obase[idx] = res;
        }
        idx += 256; r += 4; cell += 4;
        if (r >= 63) { r -= 63; cell++; }
    }
}

// ---------------------------------------------------------------------------
extern "C" void kernel_launch(void* const* d_in, const int* in_sizes, int n_in,
                              void* d_out, int out_size)
{
    const float* img     = (const float*)d_in[0];
    const float* w_patch = (const float*)d_in[1];
    const float* w_reg   = (const float*)d_in[2];
    const float* b_reg   = (const float*)d_in[3];
    const float* w_obj   = (const float*)d_in[4];
    const float* b_obj   = (const float*)d_in[5];
    float* out = (float*)d_out;

    kA<<<dim3(24, 8), 384>>>(w_patch, w_reg, w_obj);

    cudaFuncSetAttribute(kB, cudaFuncAttributeMaxDynamicSharedMemorySize, SMEMB);
    kB<<<2048, 256, SMEMB>>>(img, b_reg, b_obj, out);
}

// round 16
// speedup vs baseline: 1.7320x; 1.0564x over previous
#include <cuda_runtime.h>
#include <cuda_bf16.h>
#include <cstdint>

// ============================================================================
// out = patches @ (w_patch @ [w_reg|w_obj]) + bias, anchor decode.
// TWO kernels:
//   kA : W2 fold. 384 CTAs (grid 24x16, d-chunks of 48) compute partials,
//        self-resetting grid barrier, each CTA reduces 24 outputs (16
//        partials) into bf16 px-permuted HMMA fragments.
//        __launch_bounds__(384,3) guarantees >=444 co-resident (no deadlock).
//   kB : R9-proven HMMA GEMM (K-split x4, N-split x2, px-permuted A
//        fragments as 2xLDG.128 __ldcs, B 1-ahead __ldg), grid 2048 x 256.
// ============================================================================

__device__ float g_part[16 * 12 * 768 * 4];              // [p][jq][pc][4]
__device__ __align__(16) unsigned int g_Bfrag[48 * 6 * 32 * 2];
__device__ unsigned int g_c1;   // arrival counter (self-resets each run)
__device__ unsigned int g_c2;   // completion counter (self-resets each run)

// ---------------------------------------------------------------------------
// kA: grid (24, 16), block 384. Phase 1: partial W2 (rows r0..r0+31 x
// d-chunk of 48). Grid barrier. Phase 2: reduce 24 float4 outputs per CTA.
// ---------------------------------------------------------------------------
__global__ void __launch_bounds__(384, 3) kA(const float* __restrict__ w_patch,
                                             const float* __restrict__ w_reg,
                                             const float* __restrict__ w_obj)
{
    __shared__ __align__(16) float sWc[48 * 48];
    __shared__ float sWp[32 * 49];

    const int tid = threadIdx.x;
    const int r0  = blockIdx.x * 32;
    const int d0  = blockIdx.y * 48;

    // ---- phase 1: partial compute ----
    #pragma unroll
    for (int i = tid; i < 48 * 48; i += 384) {
        int d = i / 48, j = i % 48;
        float v = 0.f;
        if (j < 36)       v = w_reg[(size_t)(d0 + d) * 36 + j];
        else if (j < 45)  v = w_obj[(size_t)(d0 + d) * 9 + (j - 36)];
        sWc[i] = v;
    }
    #pragma unroll
    for (int i = tid; i < 32 * 48; i += 384) {
        int r = i / 48, d = i % 48;
        sWp[r * 49 + d] = w_patch[(size_t)(r0 + r) * 768 + d0 + d];
    }
    __syncthreads();

    const int jq = tid >> 5;          // 0..11, warp-uniform -> broadcast LDS
    const int rl = tid & 31;
    float4 acc = make_float4(0.f, 0.f, 0.f, 0.f);
    #pragma unroll 8
    for (int dd = 0; dd < 48; ++dd) {
        float4 w = *(const float4*)&sWc[dd * 48 + jq * 4];
        float  a = sWp[rl * 49 + dd];
        acc.x += a * w.x; acc.y += a * w.y; acc.z += a * w.z; acc.w += a * w.w;
    }
    ((float4*)g_part)[((size_t)blockIdx.y * 12 + jq) * 768 + r0 + rl] = acc;

    // ---- grid barrier (384 CTAs co-resident: >=3 CTAs/SM guaranteed) ----
    __threadfence();
    __syncthreads();
    if (tid == 0) {
        atomicAdd(&g_c1, 1u);
        while (*(volatile unsigned int*)&g_c1 < 384u) { }
    }
    __syncthreads();
    __threadfence();

    // ---- phase 2: this CTA reduces outputs [slice*24, slice*24+24) ----
    const int slice = blockIdx.y * 24 + blockIdx.x;   // 0..383
    if (tid < 24) {
        const int o   = slice * 24 + tid;             // float4 output index
        const int pc  = o % 768;
        const int jqo = o / 768;
        const float4* p4 = (const float4*)g_part;
        float4 s = make_float4(0.f, 0.f, 0.f, 0.f);
        #pragma unroll
        for (int p = 0; p < 16; ++p) {
            float4 v = p4[(size_t)p * 9216 + o];
            s.x += v.x; s.y += v.y; s.z += v.z; s.w += v.w;
        }
        float sv[4] = {s.x, s.y, s.z, s.w};
        // px-permuted frag mapping
        const int st = pc >> 4, px = pc & 15;
        const int q = px & 3, t4p = px >> 2;
        const int k = (q < 2) ? (2 * t4p + q) : (8 + 2 * t4p + (q - 2));
        unsigned short* dst = (unsigned short*)g_Bfrag;
        #pragma unroll
        for (int c = 0; c < 4; ++c) {
            int j = jqo * 4 + c;
            int tf = j >> 3;
            int lane = ((j & 7) << 2) | ((k >> 1) & 3);
            __nv_bfloat16 v = __float2bfloat16_rn(sv[c]);
            dst[(((st * 6 + tf) * 32 + lane) * 2 + (k >> 3)) * 2 + (k & 1)] =
                *(unsigned short*)&v;
        }
    }
    __syncthreads();

    // ---- completion count; last CTA resets counters for next invocation --
    if (tid == 0) {
        __threadfence();
        unsigned int r = atomicAdd(&g_c2, 1u);
        if (r == 383u) {
            atomicExch(&g_c1, 0u);
            atomicExch(&g_c2, 0u);
        }
    }
}

// ---------------------------------------------------------------------------
// kB: R9-proven. grid 2048 = ((b*32 + fy)*2 + cg), block 256 = 8 warps.
// Warp w: ks = w>>1 (12 K-steps), ns = w&1 (3 B-tiles). 16 cells/CTA.
// ---------------------------------------------------------------------------
#define SPART_OFF 0
#define BIAS_OFF  12544
#define TK_OFF    12736
#define TQ_OFF    12800
#define TBW_OFF   12864
#define TBH_OFF   12912
#define SMEMB     12992

__global__ void __launch_bounds__(256, 5) kB(
    const float* __restrict__ img,
    const float* __restrict__ b_reg,
    const float* __restrict__ b_obj,
    float* __restrict__ out)
{
    extern __shared__ __align__(16) char sm[];
    const int tid  = threadIdx.x;
    const int wid  = tid >> 5;
    const int lane = tid & 31;
    const int cg   = blockIdx.x & 1;
    const int fy   = (blockIdx.x >> 1) & 31;
    const int b    = blockIdx.x >> 6;

    if (tid < 48) ((float*)(sm + BIAS_OFF))[tid] =
        (tid < 36) ? b_reg[tid] : ((tid < 45) ? b_obj[tid - 36] : 0.f);
    if (tid < 63) {
        ((unsigned char*)(sm + TK_OFF))[tid] = (unsigned char)(tid / 7);
        ((unsigned char*)(sm + TQ_OFF))[tid] = (unsigned char)(tid % 7);
    }
    if (tid < 9) {
        ((float*)(sm + TBW_OFF))[tid] = (float)(2 << (tid % 3));
        ((float*)(sm + TBH_OFF))[tid] = (float)(2 << (tid / 3));
    }

    const int ks = wid >> 1;
    const int ns = wid & 1;
    const int g  = lane >> 2;
    const int t4 = lane & 3;
    const int s0 = ks * 12;

    const float* base = img + ((size_t)(b * 3) * 512 + (size_t)fy * 16) * 512
                      + (cg * 16 + g) * 16 + 4 * t4;

    #define SOFF(s) ((size_t)((((s) >> 4) << 9) + ((s) & 15)) << 9)

    float d[3][4];
    #pragma unroll
    for (int t = 0; t < 3; ++t)
        #pragma unroll
        for (int q = 0; q < 4; ++q) d[t][q] = 0.f;

    const uint2* __restrict__ Bf = (const uint2*)g_Bfrag;

    #define LOADA(d0_, d1_, s) do {                  \
        const float* p_ = base + SOFF(s);            \
        d0_ = __ldcs((const float4*)(p_));           \
        d1_ = __ldcs((const float4*)(p_ + 128));     \
    } while (0)

    #define LOADB(B_, s) do {                                    \
        _Pragma("unroll")                                        \
        for (int t_ = 0; t_ < 3; ++t_)                           \
            B_[t_] = __ldg(&Bf[((s) * 6 + ns * 3 + t_) * 32 + lane]); \
    } while (0)

    #define COMPUTE(f0_, f1_, B_) do {                                        \
        uint32_t a0_, a1_, a2_, a3_;                                          \
        { __nv_bfloat162 h_ = __float22bfloat162_rn(make_float2(f0_.x, f0_.y)); a0_ = *(uint32_t*)&h_; } \
        { __nv_bfloat162 h_ = __float22bfloat162_rn(make_float2(f1_.x, f1_.y)); a1_ = *(uint32_t*)&h_; } \
        { __nv_bfloat162 h_ = __float22bfloat162_rn(make_float2(f0_.z, f0_.w)); a2_ = *(uint32_t*)&h_; } \
        { __nv_bfloat162 h_ = __float22bfloat162_rn(make_float2(f1_.z, f1_.w)); a3_ = *(uint32_t*)&h_; } \
        _Pragma("unroll")                                                     \
        for (int t_ = 0; t_ < 3; ++t_)                                        \
            asm volatile(                                                     \
                "mma.sync.aligned.m16n8k16.row.col.f32.bf16.bf16.f32 "        \
                "{%0,%1,%2,%3}, {%4,%5,%6,%7}, {%8,%9}, {%0,%1,%2,%3};"       \
                : "+f"(d[t_][0]), "+f"(d[t_][1]), "+f"(d[t_][2]), "+f"(d[t_][3]) \
                : "r"(a0_), "r"(a1_), "r"(a2_), "r"(a3_),                     \
                  "r"(B_[t_].x), "r"(B_[t_].y));                              \
    } while (0)

    float4 A0a, A0b, A1a, A1b;
    uint2  B0[3], B1[3];
    LOADA(A0a, A0b, s0);
    LOADA(A1a, A1b, s0 + 1);
    LOADB(B0, s0);

    #pragma unroll
    for (int i = 0; i < 6; ++i) {
        const int s  = s0 + 2 * i;
        const int n0 = (2 * i + 2 < 12) ? s + 2 : s0 + 11;
        const int n1 = (2 * i + 3 < 12) ? s + 3 : s0 + 11;
        LOADB(B1, s + 1);
        COMPUTE(A0a, A0b, B0);
        LOADA(A0a, A0b, n0);
        LOADB(B0, n0);
        COMPUTE(A1a, A1b, B1);
        LOADA(A1a, A1b, n1);
    }

    // ---- epilogue: partials to sPart[ks][16][49] (ns halves disjoint j) ----
    float* sPart = (float*)(sm + SPART_OFF);
    float* sBias = (float*)(sm + BIAS_OFF);
    #pragma unroll
    for (int cc = 0; cc < 2; ++cc) {
        const int cell = g + cc * 8;
        float* dst = sPart + (ks * 16 + cell) * 49;
        #pragma unroll
        for (int t = 0; t < 3; ++t) {
            const int j = (ns * 3 + t) * 8 + t4 * 2;
            dst[j]     = d[t][2 * cc];
            dst[j + 1] = d[t][2 * cc + 1];
        }
    }
    __syncthreads();

    // ---- reduce 4 ks partials (+bias) into sPart[0] ----
    #pragma unroll
    for (int i = 0; i < 4; ++i) {
        int idx = tid + 256 * i;
        if (idx < 16 * 49) {
            int j = idx % 49;
            if (j < 48) {
                sPart[idx] = sPart[idx] + sPart[idx + 16 * 49]
                           + sPart[idx + 2 * 16 * 49] + sPart[idx + 3 * 16 * 49]
                           + sBias[j];
            }
        }
    }
    __syncthreads();

    // ---- decode + coalesced store: 16 cells * 63 = 1008 floats ----
    const unsigned char* tK = (const unsigned char*)(sm + TK_OFF);
    const unsigned char* tQ = (const unsigned char*)(sm + TQ_OFF);
    const float* tBW = (const float*)(sm + TBW_OFF);
    const float* tBH = (const float*)(sm + TBH_OFF);
    float* obase = out + (size_t)blockIdx.x * 1008;
    const float bb_f = (float)b;
    const float fy_f = (float)fy * 16.f;
    const float fx0  = (float)(cg * 16);

    int cell = tid / 63;
    int r    = tid - cell * 63;
    int idx  = tid;
    #pragma unroll
    for (int i = 0; i < 4; ++i) {
        if (idx < 1008) {
            const int k = tK[r], q = tQ[r];
            const float* v = sPart + cell * 49;
            float res;
            if (q == 0)      res = (fx0 + (float)cell) * 16.f + v[4 * k];
            else if (q == 1) res = fy_f + v[4 * k + 1];
            else if (q == 2) res = (fx0 + (float)cell) * 16.f + v[4 * k] + tBW[k] * v[4 * k + 2];
            else if (q == 3) res = fy_f + v[4 * k + 1] + tBH[k] * v[4 * k + 3];
            else if (q == 4) res = bb_f;
            else if (q == 5) res = 1.f / (1.f + __expf(-v[36 + k]));
            else             res = (float)k;
            obase[idx] = res;
        }
        idx += 256; r += 4; cell += 4;
        if (r >= 63) { r -= 63; cell++; }
    }
}

// ---------------------------------------------------------------------------
extern "C" void kernel_launch(void* const* d_in, const int* in_sizes, int n_in,
                              void* d_out, int out_size)
{
    const float* img     = (const float*)d_in[0];
    const float* w_patch = (const float*)d_in[1];
    const float* w_reg   = (const float*)d_in[2];
    const float* b_reg   = (const float*)d_in[3];
    const float* w_obj   = (const float*)d_in[4];
    const float* b_obj   = (const float*)d_in[5];
    float* out = (float*)d_out;

    kA<<<dim3(24, 16), 384>>>(w_patch, w_reg, w_obj);

    cudaFuncSetAttribute(kB, cudaFuncAttributeMaxDynamicSharedMemorySize, SMEMB);
    kB<<<2048, 256, SMEMB>>>(img, b_reg, b_obj, out);
}